// round 7
// baseline (speedup 1.0000x reference)
#include <cuda_runtime.h>
#include <cuda_bf16.h>
#include <cstdint>

#define N_NODE   100000
#define NODE_PAD 100096
#define D_IN     256
#define D_OUT    64
#define E_MAX    1600000
#define NEG_SLOPE 0.2f
#define SLD 40   // smem row stride in bf16 elems (80B)

// ---- scratch (__device__ globals; no allocation at runtime) ----
__device__ float g_xl[NODE_PAD * D_IN];
__device__ float g_xr[NODE_PAD * D_IN];
__device__ __nv_bfloat16 g_Ahi[NODE_PAD * D_IN];
__device__ __nv_bfloat16 g_Alo[NODE_PAD * D_IN];
__device__ __nv_bfloat16 g_Bhi[512 * 256];   // rows 0-255: Wl^T, 256-511: Wr^T ([n][k])
__device__ __nv_bfloat16 g_Blo[512 * 256];
__device__ int   g_cnt[N_NODE];
__device__ int   g_incl[N_NODE];
__device__ int   g_cursor[N_NODE];
__device__ int   g_srcs[E_MAX];
__device__ int   g_bsum[256];

// ============================================================
// Prep: fp32 -> bf16 hi/lo split
// ============================================================
__global__ void prepA_k(const float4* __restrict__ emb4, int n4, int np4)
{
    int i = blockIdx.x * blockDim.x + threadIdx.x;
    if (i >= np4) return;
    float4 v = (i < n4) ? emb4[i] : make_float4(0.f, 0.f, 0.f, 0.f);
    __nv_bfloat16 h0 = __float2bfloat16(v.x), h1 = __float2bfloat16(v.y);
    __nv_bfloat16 h2 = __float2bfloat16(v.z), h3 = __float2bfloat16(v.w);
    __nv_bfloat16 l0 = __float2bfloat16(v.x - __bfloat162float(h0));
    __nv_bfloat16 l1 = __float2bfloat16(v.y - __bfloat162float(h1));
    __nv_bfloat16 l2 = __float2bfloat16(v.z - __bfloat162float(h2));
    __nv_bfloat16 l3 = __float2bfloat16(v.w - __bfloat162float(h3));
    __nv_bfloat162* hp = (__nv_bfloat162*)g_Ahi;
    __nv_bfloat162* lp = (__nv_bfloat162*)g_Alo;
    __nv_bfloat162 a; a.x = h0; a.y = h1;
    __nv_bfloat162 b; b.x = h2; b.y = h3;
    hp[2 * i] = a; hp[2 * i + 1] = b;
    a.x = l0; a.y = l1; b.x = l2; b.y = l3;
    lp[2 * i] = a; lp[2 * i + 1] = b;
}

__global__ void prepW_k(const float* __restrict__ Wl, const float* __restrict__ Wr)
{
    int idx = blockIdx.x * blockDim.x + threadIdx.x;   // 512*256
    if (idx >= 512 * 256) return;
    int n = idx >> 8, k = idx & 255;
    float v = (n < 256) ? Wl[k * 256 + n] : Wr[k * 256 + (n - 256)];
    __nv_bfloat16 h = __float2bfloat16(v);
    g_Bhi[idx] = h;
    g_Blo[idx] = __float2bfloat16(v - __bfloat162float(h));
}

// ============================================================
// mma.sync bf16 GEMM, cp.async double-buffered, ldmatrix frags.
// C[NODE_PAD,512] = A x [Wl|Wr]^T (bf16x3: AhBh + AhBl + AlBh)
// CTA 128x128, 8 warps of 32x64, K staged 32-wide.
// ============================================================
__device__ __forceinline__ void mma16816(float c[4], const uint32_t a[4],
                                         const uint32_t b0, const uint32_t b1)
{
    asm volatile(
        "mma.sync.aligned.m16n8k16.row.col.f32.bf16.bf16.f32 "
        "{%0,%1,%2,%3}, {%4,%5,%6,%7}, {%8,%9}, {%0,%1,%2,%3};"
        : "+f"(c[0]), "+f"(c[1]), "+f"(c[2]), "+f"(c[3])
        : "r"(a[0]), "r"(a[1]), "r"(a[2]), "r"(a[3]), "r"(b0), "r"(b1));
}

__device__ __forceinline__ void ldsm4(uint32_t r[4], uint32_t addr)
{
    asm volatile("ldmatrix.sync.aligned.m8n8.x4.shared.b16 {%0,%1,%2,%3}, [%4];"
                 : "=r"(r[0]), "=r"(r[1]), "=r"(r[2]), "=r"(r[3]) : "r"(addr));
}

__device__ __forceinline__ void cpa16(uint32_t dst, const void* src)
{
    asm volatile("cp.async.ca.shared.global [%0], [%1], 16;"
                 :: "r"(dst), "l"(src));
}

#define TILE_B 10240           // bytes per tile (128*SLD*2)
#define STAGE_B (4 * TILE_B)   // Ah, Al, Bh, Bl

__global__ void __launch_bounds__(256, 1)
gemm_mma()
{
    extern __shared__ __align__(16) char smem[];
    uint32_t sb;
    asm("{ .reg .u64 t; cvta.to.shared.u64 t, %1; cvt.u32.u64 %0, t; }"
        : "=r"(sb) : "l"(smem));

    const int tid = threadIdx.x;
    const int wid = tid >> 5;
    const int lane = tid & 31;
    const int g = lane >> 2;
    const int t = lane & 3;
    const int m0 = blockIdx.y * 128;
    const int n0 = blockIdx.x * 128;
    const int wm = (wid & 3) * 32;
    const int wn = (wid >> 2) * 64;

    int r0i = tid >> 2, q0i = tid & 3;
    int r1i = (tid + 256) >> 2, q1i = tid & 3;

    float acc[2][8][4];
#pragma unroll
    for (int i = 0; i < 2; i++)
#pragma unroll
        for (int j = 0; j < 8; j++)
#pragma unroll
            for (int q = 0; q < 4; q++) acc[i][j][q] = 0.f;

    auto stage_load = [&](int s, int kt) {
        uint32_t st = sb + s * STAGE_B;
#pragma unroll
        for (int i = 0; i < 2; i++) {
            int r = i ? r1i : r0i, q = i ? q1i : q0i;
            size_t ga = (size_t)(m0 + r) * 256 + kt * 32 + q * 8;
            size_t gb = (size_t)(n0 + r) * 256 + kt * 32 + q * 8;
            uint32_t so = (uint32_t)(r * SLD + q * 8) * 2;
            cpa16(st + so,              g_Ahi + ga);
            cpa16(st + TILE_B + so,     g_Alo + ga);
            cpa16(st + 2 * TILE_B + so, g_Bhi + gb);
            cpa16(st + 3 * TILE_B + so, g_Blo + gb);
        }
        asm volatile("cp.async.commit_group;" ::: "memory");
    };

    stage_load(0, 0);

    for (int kt = 0; kt < 8; kt++) {
        if (kt < 7) {
            stage_load((kt + 1) & 1, kt + 1);
            asm volatile("cp.async.wait_group 1;" ::: "memory");
        } else {
            asm volatile("cp.async.wait_group 0;" ::: "memory");
        }
        __syncthreads();

        uint32_t st = sb + (kt & 1) * STAGE_B;
        uint32_t bAh = st, bAl = st + TILE_B;
        uint32_t bBh = st + 2 * TILE_B, bBl = st + 3 * TILE_B;

#pragma unroll
        for (int kk = 0; kk < 32; kk += 16) {
            uint32_t ah[2][4], al[2][4];
            int arow = (lane & 15);
            int akch = kk + ((lane >> 4) << 3);
#pragma unroll
            for (int mi = 0; mi < 2; mi++) {
                uint32_t ao = (uint32_t)((wm + mi * 16 + arow) * SLD + akch) * 2;
                ldsm4(ah[mi], bAh + ao);
                ldsm4(al[mi], bAl + ao);
            }
            int brow = (lane & 7) + ((lane >> 4) << 3);
            int bkch = kk + (((lane >> 3) & 1) << 3);
#pragma unroll
            for (int npi = 0; npi < 4; npi++) {
                uint32_t bo =
                    (uint32_t)((wn + npi * 16 + brow) * SLD + bkch) * 2;
                uint32_t bh[4], bl[4];
                ldsm4(bh, bBh + bo);
                ldsm4(bl, bBl + bo);
                int n0i = npi * 2, n1i = npi * 2 + 1;
                mma16816(acc[0][n0i], ah[0], bh[0], bh[1]);
                mma16816(acc[1][n0i], ah[1], bh[0], bh[1]);
                mma16816(acc[0][n1i], ah[0], bh[2], bh[3]);
                mma16816(acc[1][n1i], ah[1], bh[2], bh[3]);
                mma16816(acc[0][n0i], ah[0], bl[0], bl[1]);
                mma16816(acc[1][n0i], ah[1], bl[0], bl[1]);
                mma16816(acc[0][n1i], ah[0], bl[2], bl[3]);
                mma16816(acc[1][n1i], ah[1], bl[2], bl[3]);
                mma16816(acc[0][n0i], al[0], bh[0], bh[1]);
                mma16816(acc[1][n0i], al[1], bh[0], bh[1]);
                mma16816(acc[0][n1i], al[0], bh[2], bh[3]);
                mma16816(acc[1][n1i], al[1], bh[2], bh[3]);
            }
        }
        __syncthreads();
    }

#pragma unroll
    for (int mi = 0; mi < 2; mi++) {
        int row = m0 + wm + 16 * mi + g;
#pragma unroll
        for (int ni = 0; ni < 8; ni++) {
            int nc = n0 + wn + ni * 8 + t * 2;
            float* base = (nc < 256) ? g_xl : g_xr;
            int col = nc & 255;
            *(float2*)&base[(size_t)row * 256 + col] =
                make_float2(acc[mi][ni][0], acc[mi][ni][1]);
            *(float2*)&base[(size_t)(row + 8) * 256 + col] =
                make_float2(acc[mi][ni][2], acc[mi][ni][3]);
        }
    }
}

// ============================================================
// CSR construction  (edge_index int32: row 0 = src, row 1 = dst)
// ============================================================
__global__ void zero_cnt_k(int M)
{
    int i = blockIdx.x * blockDim.x + threadIdx.x;
    if (i < M) g_cnt[i] = 0;
}

__global__ void count_k(const int* __restrict__ ei, int E)
{
    int e = blockIdx.x * blockDim.x + threadIdx.x;
    if (e < E) atomicAdd(&g_cnt[ei[E + e]], 1);
}

__global__ void scan1_k(int M)
{
    __shared__ int s[1024];
    int gi = blockIdx.x * 1024 + threadIdx.x;
    int v = (gi < M) ? g_cnt[gi] : 0;
    s[threadIdx.x] = v;
    __syncthreads();
#pragma unroll
    for (int off = 1; off < 1024; off <<= 1) {
        int tv = (threadIdx.x >= off) ? s[threadIdx.x - off] : 0;
        __syncthreads();
        s[threadIdx.x] += tv;
        __syncthreads();
    }
    if (gi < M) g_incl[gi] = s[threadIdx.x];
    if (threadIdx.x == 1023) g_bsum[blockIdx.x] = s[1023];
}

__global__ void scan2_k(int nb)
{
    if (threadIdx.x == 0 && blockIdx.x == 0) {
        int run = 0;
        for (int b = 0; b < nb; b++) { int tv = g_bsum[b]; g_bsum[b] = run; run += tv; }
    }
}

__global__ void scan3_k(int M)
{
    int i = blockIdx.x * blockDim.x + threadIdx.x;
    if (i < M) {
        int incl = g_incl[i] + g_bsum[i >> 10];
        g_incl[i] = incl;
        g_cursor[i] = incl - g_cnt[i];
    }
}

__global__ void scatter_k(const int* __restrict__ ei, int E)
{
    int e = blockIdx.x * blockDim.x + threadIdx.x;
    if (e < E) {
        int d = ei[E + e];
        int pos = atomicAdd(&g_cursor[d], 1);
        g_srcs[pos] = ei[e];
    }
}

// ============================================================
// GATv2 attention + aggregation, one warp per dst node.
// Lane l owns channels 8l..8l+7 (head l>>3). Dual online-softmax
// state (even/odd edges) for 2x MLP; exact associative merge.
// xr/srcs/out use evict-first hints so xl owns L2.
// ============================================================
__device__ __forceinline__ float leaky4dot(float4 xl, float4 xr, float4 at)
{
    float z0 = xl.x + xr.x, z1 = xl.y + xr.y, z2 = xl.z + xr.z, z3 = xl.w + xr.w;
    float l0 = z0 > 0.f ? z0 : NEG_SLOPE * z0;
    float l1 = z1 > 0.f ? z1 : NEG_SLOPE * z1;
    float l2 = z2 > 0.f ? z2 : NEG_SLOPE * z2;
    float l3 = z3 > 0.f ? z3 : NEG_SLOPE * z3;
    return at.x * l0 + at.y * l1 + at.z * l2 + at.w * l3;
}

__global__ void __launch_bounds__(256)
agg_k(const float* __restrict__ att, const float* __restrict__ bias,
      float* __restrict__ out, int M)
{
    const int gwarp = (blockIdx.x * blockDim.x + threadIdx.x) >> 5;
    const int lane = threadIdx.x & 31;
    if (gwarp >= M) return;
    const int i = gwarp;
    const int c0 = lane * 8;

    float4 atA = *(const float4*)&att[c0];
    float4 atB = *(const float4*)&att[c0 + 4];
    const float* xrp = g_xr + (size_t)i * D_IN;
    float4 xrA = __ldcs((const float4*)&xrp[c0]);
    float4 xrB = __ldcs((const float4*)&xrp[c0 + 4]);

    // state 1 (self loop + even edges), state 2 (odd edges)
    float m1, d1, m2 = -3e38f, d2 = 0.f;
    float4 a1A, a1B;
    float4 a2A = make_float4(0.f, 0.f, 0.f, 0.f);
    float4 a2B = make_float4(0.f, 0.f, 0.f, 0.f);

    {
        const float* xlp = g_xl + (size_t)i * D_IN;
        float4 xlA = *(const float4*)&xlp[c0];
        float4 xlB = *(const float4*)&xlp[c0 + 4];
        float p = leaky4dot(xlA, xrA, atA) + leaky4dot(xlB, xrB, atB);
        p += __shfl_xor_sync(0xffffffffu, p, 1);
        p += __shfl_xor_sync(0xffffffffu, p, 2);
        p += __shfl_xor_sync(0xffffffffu, p, 4);
        m1 = p; d1 = 1.f;
        a1A = xlA; a1B = xlB;
    }

    const int end = g_incl[i];
    int j = end - g_cnt[i];

    if (j < end) {
        int s0 = __ldcs(&g_srcs[j]);
        const float* x0 = g_xl + (size_t)s0 * D_IN;
        float4 cA0 = *(const float4*)&x0[c0];
        float4 cB0 = *(const float4*)&x0[c0 + 4];
        float4 cA1 = cA0, cB1 = cB0;
        bool have1 = (j + 1 < end);
        if (have1) {
            int s1 = __ldcs(&g_srcs[j + 1]);
            const float* x1 = g_xl + (size_t)s1 * D_IN;
            cA1 = *(const float4*)&x1[c0];
            cB1 = *(const float4*)&x1[c0 + 4];
        }
        for (;;) {
            int jn = j + 2;
            bool hn0 = (jn < end), hn1 = (jn + 1 < end);
            float4 nA0, nB0, nA1, nB1;
            if (hn0) {
                int s = __ldcs(&g_srcs[jn]);
                const float* xp = g_xl + (size_t)s * D_IN;
                nA0 = *(const float4*)&xp[c0];
                nB0 = *(const float4*)&xp[c0 + 4];
            }
            if (hn1) {
                int s = __ldcs(&g_srcs[jn + 1]);
                const float* xp = g_xl + (size_t)s * D_IN;
                nA1 = *(const float4*)&xp[c0];
                nB1 = *(const float4*)&xp[c0 + 4];
            }

            float p0 = leaky4dot(cA0, xrA, atA) + leaky4dot(cB0, xrB, atB);
            float p1 = leaky4dot(cA1, xrA, atA) + leaky4dot(cB1, xrB, atB);
#pragma unroll
            for (int o = 1; o <= 4; o <<= 1) {
                p0 += __shfl_xor_sync(0xffffffffu, p0, o);
                p1 += __shfl_xor_sync(0xffffffffu, p1, o);
            }

            {
                float mn = fmaxf(m1, p0);
                float cw = __expf(m1 - mn), ww = __expf(p0 - mn);
                d1 = d1 * cw + ww; m1 = mn;
                a1A.x = a1A.x * cw + ww * cA0.x;
                a1A.y = a1A.y * cw + ww * cA0.y;
                a1A.z = a1A.z * cw + ww * cA0.z;
                a1A.w = a1A.w * cw + ww * cA0.w;
                a1B.x = a1B.x * cw + ww * cB0.x;
                a1B.y = a1B.y * cw + ww * cB0.y;
                a1B.z = a1B.z * cw + ww * cB0.z;
                a1B.w = a1B.w * cw + ww * cB0.w;
            }
            if (have1) {
                float mn = fmaxf(m2, p1);
                float cw = __expf(m2 - mn), ww = __expf(p1 - mn);
                d2 = d2 * cw + ww; m2 = mn;
                a2A.x = a2A.x * cw + ww * cA1.x;
                a2A.y = a2A.y * cw + ww * cA1.y;
                a2A.z = a2A.z * cw + ww * cA1.z;
                a2A.w = a2A.w * cw + ww * cA1.w;
                a2B.x = a2B.x * cw + ww * cB1.x;
                a2B.y = a2B.y * cw + ww * cB1.y;
                a2B.z = a2B.z * cw + ww * cB1.z;
                a2B.w = a2B.w * cw + ww * cB1.w;
            }
            if (!hn0) break;
            j = jn;
            cA0 = nA0; cB0 = nB0;
            have1 = hn1;
            if (hn1) { cA1 = nA1; cB1 = nB1; }
        }
    }

    // exact merge of state 2 into state 1
    if (d2 > 0.f) {
        float mn = fmaxf(m1, m2);
        float w1 = __expf(m1 - mn), w2 = __expf(m2 - mn);
        d1 = d1 * w1 + d2 * w2;
        a1A.x = a1A.x * w1 + a2A.x * w2;
        a1A.y = a1A.y * w1 + a2A.y * w2;
        a1A.z = a1A.z * w1 + a2A.z * w2;
        a1A.w = a1A.w * w1 + a2A.w * w2;
        a1B.x = a1B.x * w1 + a2B.x * w2;
        a1B.y = a1B.y * w1 + a2B.y * w2;
        a1B.z = a1B.z * w1 + a2B.z * w2;
        a1B.w = a1B.w * w1 + a2B.w * w2;
    }

    float inv = 1.f / (d1 + 1e-16f);
    float z[8] = { a1A.x * inv, a1A.y * inv, a1A.z * inv, a1A.w * inv,
                   a1B.x * inv, a1B.y * inv, a1B.z * inv, a1B.w * inv };
    // mean over heads: lanes l, l^8, l^16, l^24 hold the same per-head channel
#pragma unroll
    for (int q = 0; q < 8; q++) {
        z[q] += __shfl_xor_sync(0xffffffffu, z[q], 8);
        z[q] += __shfl_xor_sync(0xffffffffu, z[q], 16);
    }

    if (lane < 8) {
#pragma unroll
        for (int q = 0; q < 8; q++) {
            float o = 0.25f * z[q] + bias[c0 + q];
            z[q] = o > 0.f ? o : expm1f(o);
        }
        float* dst = out + (size_t)i * D_OUT + c0;
        __stcs((float4*)dst, make_float4(z[0], z[1], z[2], z[3]));
        __stcs((float4*)(dst + 4), make_float4(z[4], z[5], z[6], z[7]));
    }
}

// ============================================================
extern "C" void kernel_launch(void* const* d_in, const int* in_sizes, int n_in,
                              void* d_out, int out_size)
{
    const int* ei        = (const int*)d_in[1];
    const float* emb     = (const float*)d_in[2];
    const float* Wl      = (const float*)d_in[3];
    const float* Wr      = (const float*)d_in[4];
    const float* att     = (const float*)d_in[5];
    const float* bias    = (const float*)d_in[6];
    float* out           = (float*)d_out;

    const int E = in_sizes[1] / 2;         // 1,600,000
    const int M = in_sizes[2] / D_IN;      // 100,000
    const int T = (M + 127) / 128;         // 782 row tiles
    const int MP = T * 128;

    const int GEMM_SMEM = 2 * STAGE_B;     // 81920 B
    static int smem_set = 0;
    if (!smem_set) {
        cudaFuncSetAttribute(gemm_mma, cudaFuncAttributeMaxDynamicSharedMemorySize,
                             GEMM_SMEM);
        smem_set = 1;
    }

    int tb = 256;
    int n4 = M * 64, np4 = MP * 64;

    // ordered so gemm_mma is the 4th launch (ncu profile slot)
    prepA_k<<<(np4 + 255) / 256, 256>>>((const float4*)emb, n4, np4);   // 1
    prepW_k<<<512, 256>>>(Wl, Wr);                                      // 2
    zero_cnt_k<<<(M + tb - 1) / tb, tb>>>(M);                           // 3
    gemm_mma<<<dim3(4, T), 256, GEMM_SMEM>>>();                         // 4
    count_k<<<(E + tb - 1) / tb, tb>>>(ei, E);                          // 5
    int nb = (M + 1023) / 1024;
    scan1_k<<<nb, 1024>>>(M);                                           // 6
    scan2_k<<<1, 32>>>(nb);                                             // 7
    scan3_k<<<(M + tb - 1) / tb, tb>>>(M);                              // 8
    scatter_k<<<(E + tb - 1) / tb, tb>>>(ei, E);                        // 9
    agg_k<<<(M + 7) / 8, 256>>>(att, bias, out, M);                     // 10

    (void)n_in; (void)out_size;
}

// round 8
// speedup vs baseline: 1.2227x; 1.2227x over previous
#include <cuda_runtime.h>
#include <cuda_bf16.h>
#include <cstdint>

#define N_NODE   100000
#define NODE_PAD 100096
#define D_IN     256
#define D_OUT    64
#define E_MAX    1600000
#define NEG_SLOPE 0.2f
#define SLD 40   // smem row stride in bf16 elems (80B)

// ---- scratch (__device__ globals; no allocation at runtime) ----
__device__ float g_xl[NODE_PAD * D_IN];
__device__ float g_xr[NODE_PAD * D_IN];
__device__ __nv_bfloat16 g_Ahi[NODE_PAD * D_IN];
__device__ __nv_bfloat16 g_Alo[NODE_PAD * D_IN];
__device__ __nv_bfloat16 g_Bhi[512 * 256];   // rows 0-255: Wl^T, 256-511: Wr^T ([n][k])
__device__ __nv_bfloat16 g_Blo[512 * 256];
__device__ int   g_cnt[N_NODE];
__device__ int   g_incl[N_NODE];
__device__ int   g_cursor[N_NODE];
__device__ int   g_srcs[E_MAX];
__device__ int   g_bsum[256];

// ============================================================
// Prep: fp32 -> bf16 hi/lo split
// ============================================================
__global__ void prepA_k(const float4* __restrict__ emb4, int n4, int np4)
{
    int i = blockIdx.x * blockDim.x + threadIdx.x;
    if (i >= np4) return;
    float4 v = (i < n4) ? emb4[i] : make_float4(0.f, 0.f, 0.f, 0.f);
    __nv_bfloat16 h0 = __float2bfloat16(v.x), h1 = __float2bfloat16(v.y);
    __nv_bfloat16 h2 = __float2bfloat16(v.z), h3 = __float2bfloat16(v.w);
    __nv_bfloat16 l0 = __float2bfloat16(v.x - __bfloat162float(h0));
    __nv_bfloat16 l1 = __float2bfloat16(v.y - __bfloat162float(h1));
    __nv_bfloat16 l2 = __float2bfloat16(v.z - __bfloat162float(h2));
    __nv_bfloat16 l3 = __float2bfloat16(v.w - __bfloat162float(h3));
    __nv_bfloat162* hp = (__nv_bfloat162*)g_Ahi;
    __nv_bfloat162* lp = (__nv_bfloat162*)g_Alo;
    __nv_bfloat162 a; a.x = h0; a.y = h1;
    __nv_bfloat162 b; b.x = h2; b.y = h3;
    hp[2 * i] = a; hp[2 * i + 1] = b;
    a.x = l0; a.y = l1; b.x = l2; b.y = l3;
    lp[2 * i] = a; lp[2 * i + 1] = b;
}

__global__ void prepW_k(const float* __restrict__ Wl, const float* __restrict__ Wr)
{
    int idx = blockIdx.x * blockDim.x + threadIdx.x;   // 512*256
    if (idx >= 512 * 256) return;
    int n = idx >> 8, k = idx & 255;
    float v = (n < 256) ? Wl[k * 256 + n] : Wr[k * 256 + (n - 256)];
    __nv_bfloat16 h = __float2bfloat16(v);
    g_Bhi[idx] = h;
    g_Blo[idx] = __float2bfloat16(v - __bfloat162float(h));
}

// ============================================================
// mma.sync bf16 GEMM, cp.async double-buffered, ldmatrix frags.
// C[NODE_PAD,512] = A x [Wl|Wr]^T (bf16x3: AhBh + AhBl + AlBh)
// Split accumulators (accH for AhBh, accL for AhBl+AlBh) to break
// HMMA RAW chains; summed in epilogue.
// ============================================================
__device__ __forceinline__ void mma16816(float c[4], const uint32_t a[4],
                                         const uint32_t b0, const uint32_t b1)
{
    asm volatile(
        "mma.sync.aligned.m16n8k16.row.col.f32.bf16.bf16.f32 "
        "{%0,%1,%2,%3}, {%4,%5,%6,%7}, {%8,%9}, {%0,%1,%2,%3};"
        : "+f"(c[0]), "+f"(c[1]), "+f"(c[2]), "+f"(c[3])
        : "r"(a[0]), "r"(a[1]), "r"(a[2]), "r"(a[3]), "r"(b0), "r"(b1));
}

__device__ __forceinline__ void ldsm4(uint32_t r[4], uint32_t addr)
{
    asm volatile("ldmatrix.sync.aligned.m8n8.x4.shared.b16 {%0,%1,%2,%3}, [%4];"
                 : "=r"(r[0]), "=r"(r[1]), "=r"(r[2]), "=r"(r[3]) : "r"(addr));
}

__device__ __forceinline__ void cpa16(uint32_t dst, const void* src)
{
    asm volatile("cp.async.ca.shared.global [%0], [%1], 16;"
                 :: "r"(dst), "l"(src));
}

#define TILE_B 10240           // bytes per tile (128*SLD*2)
#define STAGE_B (4 * TILE_B)   // Ah, Al, Bh, Bl

__global__ void __launch_bounds__(256, 1)
gemm_mma()
{
    extern __shared__ __align__(16) char smem[];
    uint32_t sb;
    asm("{ .reg .u64 t; cvta.to.shared.u64 t, %1; cvt.u32.u64 %0, t; }"
        : "=r"(sb) : "l"(smem));

    const int tid = threadIdx.x;
    const int wid = tid >> 5;
    const int lane = tid & 31;
    const int g = lane >> 2;
    const int t = tid & 3;
    const int m0 = blockIdx.y * 128;
    const int n0 = blockIdx.x * 128;
    const int wm = (wid & 3) * 32;
    const int wn = (wid >> 2) * 64;

    int r0i = tid >> 2, q0i = tid & 3;
    int r1i = (tid + 256) >> 2, q1i = tid & 3;

    float accH[2][8][4], accL[2][8][4];
#pragma unroll
    for (int i = 0; i < 2; i++)
#pragma unroll
        for (int j = 0; j < 8; j++)
#pragma unroll
            for (int q = 0; q < 4; q++) { accH[i][j][q] = 0.f; accL[i][j][q] = 0.f; }

    auto stage_load = [&](int s, int kt) {
        uint32_t st = sb + s * STAGE_B;
#pragma unroll
        for (int i = 0; i < 2; i++) {
            int r = i ? r1i : r0i, q = i ? q1i : q0i;
            size_t ga = (size_t)(m0 + r) * 256 + kt * 32 + q * 8;
            size_t gb = (size_t)(n0 + r) * 256 + kt * 32 + q * 8;
            uint32_t so = (uint32_t)(r * SLD + q * 8) * 2;
            cpa16(st + so,              g_Ahi + ga);
            cpa16(st + TILE_B + so,     g_Alo + ga);
            cpa16(st + 2 * TILE_B + so, g_Bhi + gb);
            cpa16(st + 3 * TILE_B + so, g_Blo + gb);
        }
        asm volatile("cp.async.commit_group;" ::: "memory");
    };

    stage_load(0, 0);

    for (int kt = 0; kt < 8; kt++) {
        if (kt < 7) {
            stage_load((kt + 1) & 1, kt + 1);
            asm volatile("cp.async.wait_group 1;" ::: "memory");
        } else {
            asm volatile("cp.async.wait_group 0;" ::: "memory");
        }
        __syncthreads();

        uint32_t st = sb + (kt & 1) * STAGE_B;
        uint32_t bAh = st, bAl = st + TILE_B;
        uint32_t bBh = st + 2 * TILE_B, bBl = st + 3 * TILE_B;

#pragma unroll
        for (int kk = 0; kk < 32; kk += 16) {
            uint32_t ah[2][4], al[2][4];
            int arow = (lane & 15);
            int akch = kk + ((lane >> 4) << 3);
#pragma unroll
            for (int mi = 0; mi < 2; mi++) {
                uint32_t ao = (uint32_t)((wm + mi * 16 + arow) * SLD + akch) * 2;
                ldsm4(ah[mi], bAh + ao);
                ldsm4(al[mi], bAl + ao);
            }
            int brow = (lane & 7) + ((lane >> 4) << 3);
            int bkch = kk + (((lane >> 3) & 1) << 3);
#pragma unroll
            for (int npi = 0; npi < 4; npi++) {
                uint32_t bo =
                    (uint32_t)((wn + npi * 16 + brow) * SLD + bkch) * 2;
                uint32_t bh[4], bl[4];
                ldsm4(bh, bBh + bo);
                ldsm4(bl, bBl + bo);
                int n0i = npi * 2, n1i = npi * 2 + 1;
                // hi*hi into accH (4 independent mmas)
                mma16816(accH[0][n0i], ah[0], bh[0], bh[1]);
                mma16816(accH[1][n0i], ah[1], bh[0], bh[1]);
                mma16816(accH[0][n1i], ah[0], bh[2], bh[3]);
                mma16816(accH[1][n1i], ah[1], bh[2], bh[3]);
                // hi*lo into accL (4 independent)
                mma16816(accL[0][n0i], ah[0], bl[0], bl[1]);
                mma16816(accL[1][n0i], ah[1], bl[0], bl[1]);
                mma16816(accL[0][n1i], ah[0], bl[2], bl[3]);
                mma16816(accL[1][n1i], ah[1], bl[2], bl[3]);
                // lo*hi into accL (distance 4 from prior writer)
                mma16816(accL[0][n0i], al[0], bh[0], bh[1]);
                mma16816(accL[1][n0i], al[1], bh[0], bh[1]);
                mma16816(accL[0][n1i], al[0], bh[2], bh[3]);
                mma16816(accL[1][n1i], al[1], bh[2], bh[3]);
            }
        }
        __syncthreads();
    }

#pragma unroll
    for (int mi = 0; mi < 2; mi++) {
        int row = m0 + wm + 16 * mi + g;
#pragma unroll
        for (int ni = 0; ni < 8; ni++) {
            int nc = n0 + wn + ni * 8 + t * 2;
            float* base = (nc < 256) ? g_xl : g_xr;
            int col = nc & 255;
            *(float2*)&base[(size_t)row * 256 + col] =
                make_float2(accH[mi][ni][0] + accL[mi][ni][0],
                            accH[mi][ni][1] + accL[mi][ni][1]);
            *(float2*)&base[(size_t)(row + 8) * 256 + col] =
                make_float2(accH[mi][ni][2] + accL[mi][ni][2],
                            accH[mi][ni][3] + accL[mi][ni][3]);
        }
    }
}

// ============================================================
// CSR construction  (edge_index int32: row 0 = src, row 1 = dst)
// ============================================================
__global__ void zero_cnt_k(int M)
{
    int i = blockIdx.x * blockDim.x + threadIdx.x;
    if (i < M) g_cnt[i] = 0;
}

__global__ void count_k(const int* __restrict__ ei, int E)
{
    int e = blockIdx.x * blockDim.x + threadIdx.x;
    if (e < E) atomicAdd(&g_cnt[ei[E + e]], 1);
}

__global__ void scan1_k(int M)
{
    __shared__ int s[1024];
    int gi = blockIdx.x * 1024 + threadIdx.x;
    int v = (gi < M) ? g_cnt[gi] : 0;
    s[threadIdx.x] = v;
    __syncthreads();
#pragma unroll
    for (int off = 1; off < 1024; off <<= 1) {
        int tv = (threadIdx.x >= off) ? s[threadIdx.x - off] : 0;
        __syncthreads();
        s[threadIdx.x] += tv;
        __syncthreads();
    }
    if (gi < M) g_incl[gi] = s[threadIdx.x];
    if (threadIdx.x == 1023) g_bsum[blockIdx.x] = s[1023];
}

__global__ void scan2_k(int nb)
{
    if (threadIdx.x == 0 && blockIdx.x == 0) {
        int run = 0;
        for (int b = 0; b < nb; b++) { int tv = g_bsum[b]; g_bsum[b] = run; run += tv; }
    }
}

__global__ void scan3_k(int M)
{
    int i = blockIdx.x * blockDim.x + threadIdx.x;
    if (i < M) {
        int incl = g_incl[i] + g_bsum[i >> 10];
        g_incl[i] = incl;
        g_cursor[i] = incl - g_cnt[i];
    }
}

__global__ void scatter_k(const int* __restrict__ ei, int E)
{
    int e = blockIdx.x * blockDim.x + threadIdx.x;
    if (e < E) {
        int d = ei[E + e];
        int pos = atomicAdd(&g_cursor[d], 1);
        g_srcs[pos] = ei[e];
    }
}

// ============================================================
// GATv2 attention + aggregation, one warp per dst node.
// Lane l owns channels 8l..8l+7, all in head l>>3 (64-ch heads).
// Per-edge: one 8-lane (3-SHFL) segmented reduction.  (R6 version)
// ============================================================
__device__ __forceinline__ float leaky4dot(float4 xl, float4 xr, float4 at)
{
    float z0 = xl.x + xr.x, z1 = xl.y + xr.y, z2 = xl.z + xr.z, z3 = xl.w + xr.w;
    float l0 = z0 > 0.f ? z0 : NEG_SLOPE * z0;
    float l1 = z1 > 0.f ? z1 : NEG_SLOPE * z1;
    float l2 = z2 > 0.f ? z2 : NEG_SLOPE * z2;
    float l3 = z3 > 0.f ? z3 : NEG_SLOPE * z3;
    return at.x * l0 + at.y * l1 + at.z * l2 + at.w * l3;
}

__device__ __forceinline__ float red8(float v)
{
    v += __shfl_xor_sync(0xffffffffu, v, 1);
    v += __shfl_xor_sync(0xffffffffu, v, 2);
    v += __shfl_xor_sync(0xffffffffu, v, 4);
    return v;
}

__global__ void __launch_bounds__(256)
agg_k(const float* __restrict__ att, const float* __restrict__ bias,
      float* __restrict__ out, int M)
{
    const int gwarp = (blockIdx.x * blockDim.x + threadIdx.x) >> 5;
    const int lane = threadIdx.x & 31;
    if (gwarp >= M) return;
    const int i = gwarp;
    const int c0 = lane * 8;

    float4 atA = *(const float4*)&att[c0];
    float4 atB = *(const float4*)&att[c0 + 4];
    const float* xrp = g_xr + (size_t)i * D_IN;
    float4 xrA = *(const float4*)&xrp[c0];
    float4 xrB = *(const float4*)&xrp[c0 + 4];

    float m, d;
    float4 accA, accB;

    // ---- self loop (weight exp(0)=1) ----
    {
        const float* xlp = g_xl + (size_t)i * D_IN;
        float4 xlA = *(const float4*)&xlp[c0];
        float4 xlB = *(const float4*)&xlp[c0 + 4];
        m = red8(leaky4dot(xlA, xrA, atA) + leaky4dot(xlB, xrB, atB));
        d = 1.f;
        accA = xlA; accB = xlB;
    }

    const int end = g_incl[i];
    int j = end - g_cnt[i];

    if (j < end) {
        int src = g_srcs[j];
        const float* xlp = g_xl + (size_t)src * D_IN;
        float4 nA = *(const float4*)&xlp[c0];
        float4 nB = *(const float4*)&xlp[c0 + 4];
        for (; j < end; j++) {
            float4 xlA = nA, xlB = nB;
            if (j + 1 < end) {
                int s2 = g_srcs[j + 1];
                const float* xp = g_xl + (size_t)s2 * D_IN;
                nA = *(const float4*)&xp[c0];
                nB = *(const float4*)&xp[c0 + 4];
            }
            float p = red8(leaky4dot(xlA, xrA, atA) + leaky4dot(xlB, xrB, atB));

            float mn = fmaxf(m, p);
            float cw = __expf(m - mn), ww = __expf(p - mn);
            d = d * cw + ww; m = mn;
            accA.x = accA.x * cw + ww * xlA.x;
            accA.y = accA.y * cw + ww * xlA.y;
            accA.z = accA.z * cw + ww * xlA.z;
            accA.w = accA.w * cw + ww * xlA.w;
            accB.x = accB.x * cw + ww * xlB.x;
            accB.y = accB.y * cw + ww * xlB.y;
            accB.z = accB.z * cw + ww * xlB.z;
            accB.w = accB.w * cw + ww * xlB.w;
        }
    }

    float inv = 1.f / (d + 1e-16f);
    float z[8] = { accA.x * inv, accA.y * inv, accA.z * inv, accA.w * inv,
                   accB.x * inv, accB.y * inv, accB.z * inv, accB.w * inv };
    // mean over heads: lanes l, l^8, l^16, l^24 hold the same per-head channel
#pragma unroll
    for (int q = 0; q < 8; q++) {
        z[q] += __shfl_xor_sync(0xffffffffu, z[q], 8);
        z[q] += __shfl_xor_sync(0xffffffffu, z[q], 16);
    }

    if (lane < 8) {
#pragma unroll
        for (int q = 0; q < 8; q++) {
            float o = 0.25f * z[q] + bias[c0 + q];
            z[q] = o > 0.f ? o : expm1f(o);
        }
        float* dst = out + (size_t)i * D_OUT + c0;
        *(float4*)dst = make_float4(z[0], z[1], z[2], z[3]);
        *(float4*)(dst + 4) = make_float4(z[4], z[5], z[6], z[7]);
    }
}

// ============================================================
extern "C" void kernel_launch(void* const* d_in, const int* in_sizes, int n_in,
                              void* d_out, int out_size)
{
    const int* ei        = (const int*)d_in[1];
    const float* emb     = (const float*)d_in[2];
    const float* Wl      = (const float*)d_in[3];
    const float* Wr      = (const float*)d_in[4];
    const float* att     = (const float*)d_in[5];
    const float* bias    = (const float*)d_in[6];
    float* out           = (float*)d_out;

    const int E = in_sizes[1] / 2;         // 1,600,000
    const int M = in_sizes[2] / D_IN;      // 100,000
    const int T = (M + 127) / 128;         // 782 row tiles
    const int MP = T * 128;

    const int GEMM_SMEM = 2 * STAGE_B;     // 81920 B
    static int smem_set = 0;
    if (!smem_set) {
        cudaFuncSetAttribute(gemm_mma, cudaFuncAttributeMaxDynamicSharedMemorySize,
                             GEMM_SMEM);
        smem_set = 1;
    }

    int tb = 256;
    int n4 = M * 64, np4 = MP * 64;

    // ordered so gemm_mma is the 4th launch (ncu profile slot)
    prepA_k<<<(np4 + 255) / 256, 256>>>((const float4*)emb, n4, np4);   // 1
    prepW_k<<<512, 256>>>(Wl, Wr);                                      // 2
    zero_cnt_k<<<(M + tb - 1) / tb, tb>>>(M);                           // 3
    gemm_mma<<<dim3(4, T), 256, GEMM_SMEM>>>();                         // 4
    count_k<<<(E + tb - 1) / tb, tb>>>(ei, E);                          // 5
    int nb = (M + 1023) / 1024;
    scan1_k<<<nb, 1024>>>(M);                                           // 6
    scan2_k<<<1, 32>>>(nb);                                             // 7
    scan3_k<<<(M + tb - 1) / tb, tb>>>(M);                              // 8
    scatter_k<<<(E + tb - 1) / tb, tb>>>(ei, E);                        // 9
    agg_k<<<(M + 7) / 8, 256>>>(att, bias, out, M);                     // 10

    (void)n_in; (void)out_size;
}

// round 9
// speedup vs baseline: 1.2496x; 1.0220x over previous
#include <cuda_runtime.h>
#include <cuda_bf16.h>
#include <cstdint>

#define N_NODE   100000
#define NODE_PAD 100096
#define D_IN     256
#define D_OUT    64
#define E_MAX    1600000
#define NEG_SLOPE 0.2f
#define SLD 40   // smem row stride in bf16 elems (80B)

// ---- scratch (__device__ globals; no allocation at runtime) ----
__device__ float g_xl[NODE_PAD * D_IN];
__device__ float g_xr[NODE_PAD * D_IN];
__device__ __nv_bfloat16 g_Ahi[NODE_PAD * D_IN];
__device__ __nv_bfloat16 g_Alo[NODE_PAD * D_IN];
__device__ __nv_bfloat16 g_Bhi[512 * 256];   // rows 0-255: Wl^T, 256-511: Wr^T ([n][k])
__device__ __nv_bfloat16 g_Blo[512 * 256];
__device__ int   g_cnt[N_NODE];
__device__ int   g_incl[N_NODE];
__device__ int   g_cursor[N_NODE];
__device__ int   g_srcs[E_MAX];
__device__ int   g_bsum[256];

// ============================================================
// Prep: fp32 -> bf16 hi/lo split
// ============================================================
__global__ void prepA_k(const float4* __restrict__ emb4, int n4, int np4)
{
    int i = blockIdx.x * blockDim.x + threadIdx.x;
    if (i >= np4) return;
    float4 v = (i < n4) ? emb4[i] : make_float4(0.f, 0.f, 0.f, 0.f);
    __nv_bfloat16 h0 = __float2bfloat16(v.x), h1 = __float2bfloat16(v.y);
    __nv_bfloat16 h2 = __float2bfloat16(v.z), h3 = __float2bfloat16(v.w);
    __nv_bfloat16 l0 = __float2bfloat16(v.x - __bfloat162float(h0));
    __nv_bfloat16 l1 = __float2bfloat16(v.y - __bfloat162float(h1));
    __nv_bfloat16 l2 = __float2bfloat16(v.z - __bfloat162float(h2));
    __nv_bfloat16 l3 = __float2bfloat16(v.w - __bfloat162float(h3));
    __nv_bfloat162* hp = (__nv_bfloat162*)g_Ahi;
    __nv_bfloat162* lp = (__nv_bfloat162*)g_Alo;
    __nv_bfloat162 a; a.x = h0; a.y = h1;
    __nv_bfloat162 b; b.x = h2; b.y = h3;
    hp[2 * i] = a; hp[2 * i + 1] = b;
    a.x = l0; a.y = l1; b.x = l2; b.y = l3;
    lp[2 * i] = a; lp[2 * i + 1] = b;
}

__global__ void prepW_k(const float* __restrict__ Wl, const float* __restrict__ Wr)
{
    int idx = blockIdx.x * blockDim.x + threadIdx.x;   // 512*256
    if (idx >= 512 * 256) return;
    int n = idx >> 8, k = idx & 255;
    float v = (n < 256) ? Wl[k * 256 + n] : Wr[k * 256 + (n - 256)];
    __nv_bfloat16 h = __float2bfloat16(v);
    g_Bhi[idx] = h;
    g_Blo[idx] = __float2bfloat16(v - __bfloat162float(h));
}

// ============================================================
// mma.sync bf16 GEMM, cp.async double-buffered, ldmatrix frags.
// C[NODE_PAD,512] = A x [Wl|Wr]^T (bf16x3: AhBh + AhBl + AlBh)
// CTA tile 128m x 64n, 8 warps of 32x32, 2 CTAs/SM for latency hiding.
// ============================================================
__device__ __forceinline__ void mma16816(float c[4], const uint32_t a[4],
                                         const uint32_t b0, const uint32_t b1)
{
    asm volatile(
        "mma.sync.aligned.m16n8k16.row.col.f32.bf16.bf16.f32 "
        "{%0,%1,%2,%3}, {%4,%5,%6,%7}, {%8,%9}, {%0,%1,%2,%3};"
        : "+f"(c[0]), "+f"(c[1]), "+f"(c[2]), "+f"(c[3])
        : "r"(a[0]), "r"(a[1]), "r"(a[2]), "r"(a[3]), "r"(b0), "r"(b1));
}

__device__ __forceinline__ void ldsm4(uint32_t r[4], uint32_t addr)
{
    asm volatile("ldmatrix.sync.aligned.m8n8.x4.shared.b16 {%0,%1,%2,%3}, [%4];"
                 : "=r"(r[0]), "=r"(r[1]), "=r"(r[2]), "=r"(r[3]) : "r"(addr));
}

__device__ __forceinline__ void cpa16(uint32_t dst, const void* src)
{
    asm volatile("cp.async.ca.shared.global [%0], [%1], 16;"
                 :: "r"(dst), "l"(src));
}

#define TILE_A_B 10240          // 128 rows * SLD * 2B
#define TILE_B_B 5120           // 64 rows * SLD * 2B
#define STAGE_B  (2 * TILE_A_B + 2 * TILE_B_B)   // 30720 B
// stage offsets
#define OFF_AH 0
#define OFF_AL TILE_A_B
#define OFF_BH (2 * TILE_A_B)
#define OFF_BL (2 * TILE_A_B + TILE_B_B)

__global__ void __launch_bounds__(256, 2)
gemm_mma()
{
    extern __shared__ __align__(16) char smem[];
    uint32_t sb;
    asm("{ .reg .u64 t; cvta.to.shared.u64 t, %1; cvt.u32.u64 %0, t; }"
        : "=r"(sb) : "l"(smem));

    const int tid = threadIdx.x;
    const int wid = tid >> 5;
    const int lane = tid & 31;
    const int g = lane >> 2;
    const int t = lane & 3;
    const int m0 = blockIdx.y * 128;
    const int n0 = blockIdx.x * 64;
    const int wm = (wid & 3) * 32;     // warp row base
    const int wn = (wid >> 2) * 32;    // warp col base (0 or 32)

    float acc[2][4][4];
#pragma unroll
    for (int i = 0; i < 2; i++)
#pragma unroll
        for (int j = 0; j < 4; j++)
#pragma unroll
            for (int q = 0; q < 4; q++) acc[i][j][q] = 0.f;

    auto stage_load = [&](int s, int kt) {
        uint32_t st = sb + s * STAGE_B;
        // A: 128 rows x 32 bf16 = 512 uint4 per tile; 2 chunks/thread
#pragma unroll
        for (int i = 0; i < 2; i++) {
            int idx = tid + i * 256;
            int r = idx >> 2, q = idx & 3;
            size_t ga = (size_t)(m0 + r) * 256 + kt * 32 + q * 8;
            uint32_t so = (uint32_t)(r * SLD + q * 8) * 2;
            cpa16(st + OFF_AH + so, g_Ahi + ga);
            cpa16(st + OFF_AL + so, g_Alo + ga);
        }
        // B: 64 rows x 32 bf16 = 256 uint4 per tile; 1 chunk/thread
        {
            int r = tid >> 2, q = tid & 3;
            size_t gb = (size_t)(n0 + r) * 256 + kt * 32 + q * 8;
            uint32_t so = (uint32_t)(r * SLD + q * 8) * 2;
            cpa16(st + OFF_BH + so, g_Bhi + gb);
            cpa16(st + OFF_BL + so, g_Blo + gb);
        }
        asm volatile("cp.async.commit_group;" ::: "memory");
    };

    stage_load(0, 0);

    for (int kt = 0; kt < 8; kt++) {
        if (kt < 7) {
            stage_load((kt + 1) & 1, kt + 1);
            asm volatile("cp.async.wait_group 1;" ::: "memory");
        } else {
            asm volatile("cp.async.wait_group 0;" ::: "memory");
        }
        __syncthreads();

        uint32_t st = sb + (kt & 1) * STAGE_B;
        uint32_t bAh = st + OFF_AH, bAl = st + OFF_AL;
        uint32_t bBh = st + OFF_BH, bBl = st + OFF_BL;

#pragma unroll
        for (int kk = 0; kk < 32; kk += 16) {
            uint32_t ah[2][4], al[2][4];
            int arow = (lane & 15);
            int akch = kk + ((lane >> 4) << 3);
#pragma unroll
            for (int mi = 0; mi < 2; mi++) {
                uint32_t ao = (uint32_t)((wm + mi * 16 + arow) * SLD + akch) * 2;
                ldsm4(ah[mi], bAh + ao);
                ldsm4(al[mi], bAl + ao);
            }
            int brow = (lane & 7) + ((lane >> 4) << 3);
            int bkch = kk + (((lane >> 3) & 1) << 3);
#pragma unroll
            for (int npi = 0; npi < 2; npi++) {
                uint32_t bo =
                    (uint32_t)((wn + npi * 16 + brow) * SLD + bkch) * 2;
                uint32_t bh[4], bl[4];
                ldsm4(bh, bBh + bo);
                ldsm4(bl, bBl + bo);
                int n0i = npi * 2, n1i = npi * 2 + 1;
                mma16816(acc[0][n0i], ah[0], bh[0], bh[1]);
                mma16816(acc[1][n0i], ah[1], bh[0], bh[1]);
                mma16816(acc[0][n1i], ah[0], bh[2], bh[3]);
                mma16816(acc[1][n1i], ah[1], bh[2], bh[3]);
                mma16816(acc[0][n0i], ah[0], bl[0], bl[1]);
                mma16816(acc[1][n0i], ah[1], bl[0], bl[1]);
                mma16816(acc[0][n1i], ah[0], bl[2], bl[3]);
                mma16816(acc[1][n1i], ah[1], bl[2], bl[3]);
                mma16816(acc[0][n0i], al[0], bh[0], bh[1]);
                mma16816(acc[1][n0i], al[1], bh[0], bh[1]);
                mma16816(acc[0][n1i], al[0], bh[2], bh[3]);
                mma16816(acc[1][n1i], al[1], bh[2], bh[3]);
            }
        }
        __syncthreads();
    }

#pragma unroll
    for (int mi = 0; mi < 2; mi++) {
        int row = m0 + wm + 16 * mi + g;
#pragma unroll
        for (int ni = 0; ni < 4; ni++) {
            int nc = n0 + wn + ni * 8 + t * 2;
            float* base = (nc < 256) ? g_xl : g_xr;
            int col = nc & 255;
            *(float2*)&base[(size_t)row * 256 + col] =
                make_float2(acc[mi][ni][0], acc[mi][ni][1]);
            *(float2*)&base[(size_t)(row + 8) * 256 + col] =
                make_float2(acc[mi][ni][2], acc[mi][ni][3]);
        }
    }
}

// ============================================================
// CSR construction  (edge_index int32: row 0 = src, row 1 = dst)
// ============================================================
__global__ void zero_cnt_k(int M)
{
    int i = blockIdx.x * blockDim.x + threadIdx.x;
    if (i < M) g_cnt[i] = 0;
}

__global__ void count_k(const int* __restrict__ ei, int E)
{
    int e = blockIdx.x * blockDim.x + threadIdx.x;
    if (e < E) atomicAdd(&g_cnt[ei[E + e]], 1);
}

__global__ void scan1_k(int M)
{
    __shared__ int s[1024];
    int gi = blockIdx.x * 1024 + threadIdx.x;
    int v = (gi < M) ? g_cnt[gi] : 0;
    s[threadIdx.x] = v;
    __syncthreads();
#pragma unroll
    for (int off = 1; off < 1024; off <<= 1) {
        int tv = (threadIdx.x >= off) ? s[threadIdx.x - off] : 0;
        __syncthreads();
        s[threadIdx.x] += tv;
        __syncthreads();
    }
    if (gi < M) g_incl[gi] = s[threadIdx.x];
    if (threadIdx.x == 1023) g_bsum[blockIdx.x] = s[1023];
}

__global__ void scan2_k(int nb)
{
    if (threadIdx.x == 0 && blockIdx.x == 0) {
        int run = 0;
        for (int b = 0; b < nb; b++) { int tv = g_bsum[b]; g_bsum[b] = run; run += tv; }
    }
}

__global__ void scan3_k(int M)
{
    int i = blockIdx.x * blockDim.x + threadIdx.x;
    if (i < M) {
        int incl = g_incl[i] + g_bsum[i >> 10];
        g_incl[i] = incl;
        g_cursor[i] = incl - g_cnt[i];
    }
}

__global__ void scatter_k(const int* __restrict__ ei, int E)
{
    int e = blockIdx.x * blockDim.x + threadIdx.x;
    if (e < E) {
        int d = ei[E + e];
        int pos = atomicAdd(&g_cursor[d], 1);
        g_srcs[pos] = ei[e];
    }
}

// ============================================================
// GATv2 attention + aggregation, one warp per dst node.
// Lane l owns channels 8l..8l+7, all in head l>>3 (64-ch heads).
// Per-edge: one 8-lane (3-SHFL) segmented reduction.  (R6 version)
// ============================================================
__device__ __forceinline__ float leaky4dot(float4 xl, float4 xr, float4 at)
{
    float z0 = xl.x + xr.x, z1 = xl.y + xr.y, z2 = xl.z + xr.z, z3 = xl.w + xr.w;
    float l0 = z0 > 0.f ? z0 : NEG_SLOPE * z0;
    float l1 = z1 > 0.f ? z1 : NEG_SLOPE * z1;
    float l2 = z2 > 0.f ? z2 : NEG_SLOPE * z2;
    float l3 = z3 > 0.f ? z3 : NEG_SLOPE * z3;
    return at.x * l0 + at.y * l1 + at.z * l2 + at.w * l3;
}

__device__ __forceinline__ float red8(float v)
{
    v += __shfl_xor_sync(0xffffffffu, v, 1);
    v += __shfl_xor_sync(0xffffffffu, v, 2);
    v += __shfl_xor_sync(0xffffffffu, v, 4);
    return v;
}

__global__ void __launch_bounds__(256)
agg_k(const float* __restrict__ att, const float* __restrict__ bias,
      float* __restrict__ out, int M)
{
    const int gwarp = (blockIdx.x * blockDim.x + threadIdx.x) >> 5;
    const int lane = threadIdx.x & 31;
    if (gwarp >= M) return;
    const int i = gwarp;
    const int c0 = lane * 8;

    float4 atA = *(const float4*)&att[c0];
    float4 atB = *(const float4*)&att[c0 + 4];
    const float* xrp = g_xr + (size_t)i * D_IN;
    float4 xrA = *(const float4*)&xrp[c0];
    float4 xrB = *(const float4*)&xrp[c0 + 4];

    float m, d;
    float4 accA, accB;

    // ---- self loop (weight exp(0)=1) ----
    {
        const float* xlp = g_xl + (size_t)i * D_IN;
        float4 xlA = *(const float4*)&xlp[c0];
        float4 xlB = *(const float4*)&xlp[c0 + 4];
        m = red8(leaky4dot(xlA, xrA, atA) + leaky4dot(xlB, xrB, atB));
        d = 1.f;
        accA = xlA; accB = xlB;
    }

    const int end = g_incl[i];
    int j = end - g_cnt[i];

    if (j < end) {
        int src = g_srcs[j];
        const float* xlp = g_xl + (size_t)src * D_IN;
        float4 nA = *(const float4*)&xlp[c0];
        float4 nB = *(const float4*)&xlp[c0 + 4];
        for (; j < end; j++) {
            float4 xlA = nA, xlB = nB;
            if (j + 1 < end) {
                int s2 = g_srcs[j + 1];
                const float* xp = g_xl + (size_t)s2 * D_IN;
                nA = *(const float4*)&xp[c0];
                nB = *(const float4*)&xp[c0 + 4];
            }
            float p = red8(leaky4dot(xlA, xrA, atA) + leaky4dot(xlB, xrB, atB));

            float mn = fmaxf(m, p);
            float cw = __expf(m - mn), ww = __expf(p - mn);
            d = d * cw + ww; m = mn;
            accA.x = accA.x * cw + ww * xlA.x;
            accA.y = accA.y * cw + ww * xlA.y;
            accA.z = accA.z * cw + ww * xlA.z;
            accA.w = accA.w * cw + ww * xlA.w;
            accB.x = accB.x * cw + ww * xlB.x;
            accB.y = accB.y * cw + ww * xlB.y;
            accB.z = accB.z * cw + ww * xlB.z;
            accB.w = accB.w * cw + ww * xlB.w;
        }
    }

    float inv = 1.f / (d + 1e-16f);
    float z[8] = { accA.x * inv, accA.y * inv, accA.z * inv, accA.w * inv,
                   accB.x * inv, accB.y * inv, accB.z * inv, accB.w * inv };
    // mean over heads: lanes l, l^8, l^16, l^24 hold the same per-head channel
#pragma unroll
    for (int q = 0; q < 8; q++) {
        z[q] += __shfl_xor_sync(0xffffffffu, z[q], 8);
        z[q] += __shfl_xor_sync(0xffffffffu, z[q], 16);
    }

    if (lane < 8) {
#pragma unroll
        for (int q = 0; q < 8; q++) {
            float o = 0.25f * z[q] + bias[c0 + q];
            z[q] = o > 0.f ? o : expm1f(o);
        }
        float* dst = out + (size_t)i * D_OUT + c0;
        *(float4*)dst = make_float4(z[0], z[1], z[2], z[3]);
        *(float4*)(dst + 4) = make_float4(z[4], z[5], z[6], z[7]);
    }
}

// ============================================================
extern "C" void kernel_launch(void* const* d_in, const int* in_sizes, int n_in,
                              void* d_out, int out_size)
{
    const int* ei        = (const int*)d_in[1];
    const float* emb     = (const float*)d_in[2];
    const float* Wl      = (const float*)d_in[3];
    const float* Wr      = (const float*)d_in[4];
    const float* att     = (const float*)d_in[5];
    const float* bias    = (const float*)d_in[6];
    float* out           = (float*)d_out;

    const int E = in_sizes[1] / 2;         // 1,600,000
    const int M = in_sizes[2] / D_IN;      // 100,000
    const int T = (M + 127) / 128;         // 782 row tiles
    const int MP = T * 128;

    const int GEMM_SMEM = 2 * STAGE_B;     // 61440 B
    static int smem_set = 0;
    if (!smem_set) {
        cudaFuncSetAttribute(gemm_mma, cudaFuncAttributeMaxDynamicSharedMemorySize,
                             GEMM_SMEM);
        smem_set = 1;
    }

    int tb = 256;
    int n4 = M * 64, np4 = MP * 64;

    // ordered so gemm_mma is the 4th launch (ncu profile slot)
    prepA_k<<<(np4 + 255) / 256, 256>>>((const float4*)emb, n4, np4);   // 1
    prepW_k<<<512, 256>>>(Wl, Wr);                                      // 2
    zero_cnt_k<<<(M + tb - 1) / tb, tb>>>(M);                           // 3
    gemm_mma<<<dim3(8, T), 256, GEMM_SMEM>>>();                         // 4
    count_k<<<(E + tb - 1) / tb, tb>>>(ei, E);                          // 5
    int nb = (M + 1023) / 1024;
    scan1_k<<<nb, 1024>>>(M);                                           // 6
    scan2_k<<<1, 32>>>(nb);                                             // 7
    scan3_k<<<(M + tb - 1) / tb, tb>>>(M);                              // 8
    scatter_k<<<(E + tb - 1) / tb, tb>>>(ei, E);                        // 9
    agg_k<<<(M + 7) / 8, 256>>>(att, bias, out, M);                     // 10

    (void)n_in; (void)out_size;
}

// round 10
// speedup vs baseline: 1.3608x; 1.0890x over previous
#include <cuda_runtime.h>
#include <cuda_bf16.h>
#include <cstdint>

#define N_NODE   100000
#define NODE_PAD 100096
#define D_IN     256
#define D_OUT    64
#define E_MAX    1600000
#define NEG_SLOPE 0.2f
#define SLD 40   // smem row stride in bf16 elems (80B)

// ---- scratch (__device__ globals; no allocation at runtime) ----
__device__ float g_xl[NODE_PAD * D_IN];
__device__ float g_xr[NODE_PAD * D_IN];
__device__ __nv_bfloat16 g_Ahi[NODE_PAD * D_IN];
__device__ __nv_bfloat16 g_Alo[NODE_PAD * D_IN];
__device__ __nv_bfloat16 g_Bhi[512 * 256];   // rows 0-255: Wl^T, 256-511: Wr^T ([n][k])
__device__ __nv_bfloat16 g_Blo[512 * 256];
__device__ int   g_cnt[N_NODE];
__device__ int   g_incl[N_NODE];
__device__ int   g_cursor[N_NODE];
__device__ int   g_srcs[E_MAX];
__device__ int   g_bsum[256];

// ============================================================
// Prep: fp32 -> bf16 hi/lo split
// ============================================================
__global__ void prepA_k(const float4* __restrict__ emb4, int n4, int np4)
{
    int i = blockIdx.x * blockDim.x + threadIdx.x;
    if (i >= np4) return;
    float4 v = (i < n4) ? emb4[i] : make_float4(0.f, 0.f, 0.f, 0.f);
    __nv_bfloat16 h0 = __float2bfloat16(v.x), h1 = __float2bfloat16(v.y);
    __nv_bfloat16 h2 = __float2bfloat16(v.z), h3 = __float2bfloat16(v.w);
    __nv_bfloat16 l0 = __float2bfloat16(v.x - __bfloat162float(h0));
    __nv_bfloat16 l1 = __float2bfloat16(v.y - __bfloat162float(h1));
    __nv_bfloat16 l2 = __float2bfloat16(v.z - __bfloat162float(h2));
    __nv_bfloat16 l3 = __float2bfloat16(v.w - __bfloat162float(h3));
    __nv_bfloat162* hp = (__nv_bfloat162*)g_Ahi;
    __nv_bfloat162* lp = (__nv_bfloat162*)g_Alo;
    __nv_bfloat162 a; a.x = h0; a.y = h1;
    __nv_bfloat162 b; b.x = h2; b.y = h3;
    hp[2 * i] = a; hp[2 * i + 1] = b;
    a.x = l0; a.y = l1; b.x = l2; b.y = l3;
    lp[2 * i] = a; lp[2 * i + 1] = b;
}

__global__ void prepW_k(const float* __restrict__ Wl, const float* __restrict__ Wr)
{
    int idx = blockIdx.x * blockDim.x + threadIdx.x;   // 512*256
    if (idx >= 512 * 256) return;
    int n = idx >> 8, k = idx & 255;
    float v = (n < 256) ? Wl[k * 256 + n] : Wr[k * 256 + (n - 256)];
    __nv_bfloat16 h = __float2bfloat16(v);
    g_Bhi[idx] = h;
    g_Blo[idx] = __float2bfloat16(v - __bfloat162float(h));
}

// ============================================================
// mma.sync bf16 GEMM, cp.async double-buffered, ldmatrix frags.
// C[NODE_PAD,512] = A x [Wl|Wr]^T (bf16x3: AhBh + AhBl + AlBh)
// CTA tile 128m x 128n, 4 warps of 64x64 (2x2), 2 CTAs/SM.
// Warp tile 64x64 halves smem bytes/MAC vs 32x32 (crossbar was cap).
// ============================================================
__device__ __forceinline__ void mma16816(float c[4], const uint32_t a[4],
                                         const uint32_t b0, const uint32_t b1)
{
    asm volatile(
        "mma.sync.aligned.m16n8k16.row.col.f32.bf16.bf16.f32 "
        "{%0,%1,%2,%3}, {%4,%5,%6,%7}, {%8,%9}, {%0,%1,%2,%3};"
        : "+f"(c[0]), "+f"(c[1]), "+f"(c[2]), "+f"(c[3])
        : "r"(a[0]), "r"(a[1]), "r"(a[2]), "r"(a[3]), "r"(b0), "r"(b1));
}

__device__ __forceinline__ void ldsm4(uint32_t r[4], uint32_t addr)
{
    asm volatile("ldmatrix.sync.aligned.m8n8.x4.shared.b16 {%0,%1,%2,%3}, [%4];"
                 : "=r"(r[0]), "=r"(r[1]), "=r"(r[2]), "=r"(r[3]) : "r"(addr));
}

__device__ __forceinline__ void cpa16(uint32_t dst, const void* src)
{
    asm volatile("cp.async.ca.shared.global [%0], [%1], 16;"
                 :: "r"(dst), "l"(src));
}

#define TILE_MAT 10240          // 128 rows * SLD * 2B  (each of Ah, Al, Bh, Bl)
#define STAGE_B  (4 * TILE_MAT) // 40960 B
#define OFF_AH 0
#define OFF_AL TILE_MAT
#define OFF_BH (2 * TILE_MAT)
#define OFF_BL (3 * TILE_MAT)

__global__ void __launch_bounds__(128, 2)
gemm_mma()
{
    extern __shared__ __align__(16) char smem[];
    uint32_t sb;
    asm("{ .reg .u64 t; cvta.to.shared.u64 t, %1; cvt.u32.u64 %0, t; }"
        : "=r"(sb) : "l"(smem));

    const int tid = threadIdx.x;
    const int wid = tid >> 5;          // 0..3
    const int lane = tid & 31;
    const int g = lane >> 2;
    const int t = lane & 3;
    const int m0 = blockIdx.y * 128;
    const int n0 = blockIdx.x * 128;
    const int wm = (wid & 1) * 64;     // warp row base
    const int wn = (wid >> 1) * 64;    // warp col base

    float acc[4][8][4];
#pragma unroll
    for (int i = 0; i < 4; i++)
#pragma unroll
        for (int j = 0; j < 8; j++)
#pragma unroll
            for (int q = 0; q < 4; q++) acc[i][j][q] = 0.f;

    auto stage_load = [&](int s, int kt) {
        uint32_t st = sb + s * STAGE_B;
        // each matrix: 128 rows x 32 bf16 = 512 uint4; 4 chunks/thread
#pragma unroll
        for (int i = 0; i < 4; i++) {
            int idx = tid + i * 128;
            int r = idx >> 2, q = idx & 3;
            size_t ga = (size_t)(m0 + r) * 256 + kt * 32 + q * 8;
            size_t gb = (size_t)(n0 + r) * 256 + kt * 32 + q * 8;
            uint32_t so = (uint32_t)(r * SLD + q * 8) * 2;
            cpa16(st + OFF_AH + so, g_Ahi + ga);
            cpa16(st + OFF_AL + so, g_Alo + ga);
            cpa16(st + OFF_BH + so, g_Bhi + gb);
            cpa16(st + OFF_BL + so, g_Blo + gb);
        }
        asm volatile("cp.async.commit_group;" ::: "memory");
    };

    stage_load(0, 0);

    for (int kt = 0; kt < 8; kt++) {
        if (kt < 7) {
            stage_load((kt + 1) & 1, kt + 1);
            asm volatile("cp.async.wait_group 1;" ::: "memory");
        } else {
            asm volatile("cp.async.wait_group 0;" ::: "memory");
        }
        __syncthreads();

        uint32_t st = sb + (kt & 1) * STAGE_B;
        uint32_t bAh = st + OFF_AH, bAl = st + OFF_AL;
        uint32_t bBh = st + OFF_BH, bBl = st + OFF_BL;

#pragma unroll
        for (int kk = 0; kk < 32; kk += 16) {
            // A frags: 4 mi tiles of 16 rows x 16 k (hi and lo)
            uint32_t ah[4][4], al[4][4];
            int arow = (lane & 15);
            int akch = kk + ((lane >> 4) << 3);
#pragma unroll
            for (int mi = 0; mi < 4; mi++) {
                uint32_t ao = (uint32_t)((wm + mi * 16 + arow) * SLD + akch) * 2;
                ldsm4(ah[mi], bAh + ao);
                ldsm4(al[mi], bAl + ao);
            }
            int brow = (lane & 7) + ((lane >> 4) << 3);
            int bkch = kk + (((lane >> 3) & 1) << 3);
#pragma unroll
            for (int npi = 0; npi < 4; npi++) {
                uint32_t bo =
                    (uint32_t)((wn + npi * 16 + brow) * SLD + bkch) * 2;
                uint32_t bh[4], bl[4];
                ldsm4(bh, bBh + bo);
                ldsm4(bl, bBl + bo);
                int n0i = npi * 2, n1i = npi * 2 + 1;
#pragma unroll
                for (int mi = 0; mi < 4; mi++) {
                    mma16816(acc[mi][n0i], ah[mi], bh[0], bh[1]);
                    mma16816(acc[mi][n1i], ah[mi], bh[2], bh[3]);
                }
#pragma unroll
                for (int mi = 0; mi < 4; mi++) {
                    mma16816(acc[mi][n0i], ah[mi], bl[0], bl[1]);
                    mma16816(acc[mi][n1i], ah[mi], bl[2], bl[3]);
                }
#pragma unroll
                for (int mi = 0; mi < 4; mi++) {
                    mma16816(acc[mi][n0i], al[mi], bh[0], bh[1]);
                    mma16816(acc[mi][n1i], al[mi], bh[2], bh[3]);
                }
            }
        }
        __syncthreads();
    }

#pragma unroll
    for (int mi = 0; mi < 4; mi++) {
        int row = m0 + wm + 16 * mi + g;
#pragma unroll
        for (int ni = 0; ni < 8; ni++) {
            int nc = n0 + wn + ni * 8 + t * 2;
            float* base = (nc < 256) ? g_xl : g_xr;
            int col = nc & 255;
            *(float2*)&base[(size_t)row * 256 + col] =
                make_float2(acc[mi][ni][0], acc[mi][ni][1]);
            *(float2*)&base[(size_t)(row + 8) * 256 + col] =
                make_float2(acc[mi][ni][2], acc[mi][ni][3]);
        }
    }
}

// ============================================================
// CSR construction  (edge_index int32: row 0 = src, row 1 = dst)
// ============================================================
__global__ void zero_cnt_k(int M)
{
    int i = blockIdx.x * blockDim.x + threadIdx.x;
    if (i < M) g_cnt[i] = 0;
}

__global__ void count_k(const int* __restrict__ ei, int E)
{
    int e = blockIdx.x * blockDim.x + threadIdx.x;
    if (e < E) atomicAdd(&g_cnt[ei[E + e]], 1);
}

__global__ void scan1_k(int M)
{
    __shared__ int s[1024];
    int gi = blockIdx.x * 1024 + threadIdx.x;
    int v = (gi < M) ? g_cnt[gi] : 0;
    s[threadIdx.x] = v;
    __syncthreads();
#pragma unroll
    for (int off = 1; off < 1024; off <<= 1) {
        int tv = (threadIdx.x >= off) ? s[threadIdx.x - off] : 0;
        __syncthreads();
        s[threadIdx.x] += tv;
        __syncthreads();
    }
    if (gi < M) g_incl[gi] = s[threadIdx.x];
    if (threadIdx.x == 1023) g_bsum[blockIdx.x] = s[1023];
}

__global__ void scan2_k(int nb)
{
    if (threadIdx.x == 0 && blockIdx.x == 0) {
        int run = 0;
        for (int b = 0; b < nb; b++) { int tv = g_bsum[b]; g_bsum[b] = run; run += tv; }
    }
}

__global__ void scan3_k(int M)
{
    int i = blockIdx.x * blockDim.x + threadIdx.x;
    if (i < M) {
        int incl = g_incl[i] + g_bsum[i >> 10];
        g_incl[i] = incl;
        g_cursor[i] = incl - g_cnt[i];
    }
}

__global__ void scatter_k(const int* __restrict__ ei, int E)
{
    int e = blockIdx.x * blockDim.x + threadIdx.x;
    if (e < E) {
        int d = ei[E + e];
        int pos = atomicAdd(&g_cursor[d], 1);
        g_srcs[pos] = ei[e];
    }
}

// ============================================================
// GATv2 attention + aggregation, one warp per dst node.
// Lane l owns channels 8l..8l+7, all in head l>>3 (64-ch heads).
// Per-edge: one 8-lane (3-SHFL) segmented reduction.  (R6 version)
// ============================================================
__device__ __forceinline__ float leaky4dot(float4 xl, float4 xr, float4 at)
{
    float z0 = xl.x + xr.x, z1 = xl.y + xr.y, z2 = xl.z + xr.z, z3 = xl.w + xr.w;
    float l0 = z0 > 0.f ? z0 : NEG_SLOPE * z0;
    float l1 = z1 > 0.f ? z1 : NEG_SLOPE * z1;
    float l2 = z2 > 0.f ? z2 : NEG_SLOPE * z2;
    float l3 = z3 > 0.f ? z3 : NEG_SLOPE * z3;
    return at.x * l0 + at.y * l1 + at.z * l2 + at.w * l3;
}

__device__ __forceinline__ float red8(float v)
{
    v += __shfl_xor_sync(0xffffffffu, v, 1);
    v += __shfl_xor_sync(0xffffffffu, v, 2);
    v += __shfl_xor_sync(0xffffffffu, v, 4);
    return v;
}

__global__ void __launch_bounds__(256)
agg_k(const float* __restrict__ att, const float* __restrict__ bias,
      float* __restrict__ out, int M)
{
    const int gwarp = (blockIdx.x * blockDim.x + threadIdx.x) >> 5;
    const int lane = threadIdx.x & 31;
    if (gwarp >= M) return;
    const int i = gwarp;
    const int c0 = lane * 8;

    float4 atA = *(const float4*)&att[c0];
    float4 atB = *(const float4*)&att[c0 + 4];
    const float* xrp = g_xr + (size_t)i * D_IN;
    float4 xrA = *(const float4*)&xrp[c0];
    float4 xrB = *(const float4*)&xrp[c0 + 4];

    float m, d;
    float4 accA, accB;

    // ---- self loop (weight exp(0)=1) ----
    {
        const float* xlp = g_xl + (size_t)i * D_IN;
        float4 xlA = *(const float4*)&xlp[c0];
        float4 xlB = *(const float4*)&xlp[c0 + 4];
        m = red8(leaky4dot(xlA, xrA, atA) + leaky4dot(xlB, xrB, atB));
        d = 1.f;
        accA = xlA; accB = xlB;
    }

    const int end = g_incl[i];
    int j = end - g_cnt[i];

    if (j < end) {
        int src = g_srcs[j];
        const float* xlp = g_xl + (size_t)src * D_IN;
        float4 nA = *(const float4*)&xlp[c0];
        float4 nB = *(const float4*)&xlp[c0 + 4];
        for (; j < end; j++) {
            float4 xlA = nA, xlB = nB;
            if (j + 1 < end) {
                int s2 = g_srcs[j + 1];
                const float* xp = g_xl + (size_t)s2 * D_IN;
                nA = *(const float4*)&xp[c0];
                nB = *(const float4*)&xp[c0 + 4];
            }
            float p = red8(leaky4dot(xlA, xrA, atA) + leaky4dot(xlB, xrB, atB));

            float mn = fmaxf(m, p);
            float cw = __expf(m - mn), ww = __expf(p - mn);
            d = d * cw + ww; m = mn;
            accA.x = accA.x * cw + ww * xlA.x;
            accA.y = accA.y * cw + ww * xlA.y;
            accA.z = accA.z * cw + ww * xlA.z;
            accA.w = accA.w * cw + ww * xlA.w;
            accB.x = accB.x * cw + ww * xlB.x;
            accB.y = accB.y * cw + ww * xlB.y;
            accB.z = accB.z * cw + ww * xlB.z;
            accB.w = accB.w * cw + ww * xlB.w;
        }
    }

    float inv = 1.f / (d + 1e-16f);
    float z[8] = { accA.x * inv, accA.y * inv, accA.z * inv, accA.w * inv,
                   accB.x * inv, accB.y * inv, accB.z * inv, accB.w * inv };
    // mean over heads: lanes l, l^8, l^16, l^24 hold the same per-head channel
#pragma unroll
    for (int q = 0; q < 8; q++) {
        z[q] += __shfl_xor_sync(0xffffffffu, z[q], 8);
        z[q] += __shfl_xor_sync(0xffffffffu, z[q], 16);
    }

    if (lane < 8) {
#pragma unroll
        for (int q = 0; q < 8; q++) {
            float o = 0.25f * z[q] + bias[c0 + q];
            z[q] = o > 0.f ? o : expm1f(o);
        }
        float* dst = out + (size_t)i * D_OUT + c0;
        *(float4*)dst = make_float4(z[0], z[1], z[2], z[3]);
        *(float4*)(dst + 4) = make_float4(z[4], z[5], z[6], z[7]);
    }
}

// ============================================================
extern "C" void kernel_launch(void* const* d_in, const int* in_sizes, int n_in,
                              void* d_out, int out_size)
{
    const int* ei        = (const int*)d_in[1];
    const float* emb     = (const float*)d_in[2];
    const float* Wl      = (const float*)d_in[3];
    const float* Wr      = (const float*)d_in[4];
    const float* att     = (const float*)d_in[5];
    const float* bias    = (const float*)d_in[6];
    float* out           = (float*)d_out;

    const int E = in_sizes[1] / 2;         // 1,600,000
    const int M = in_sizes[2] / D_IN;      // 100,000
    const int T = (M + 127) / 128;         // 782 row tiles
    const int MP = T * 128;

    const int GEMM_SMEM = 2 * STAGE_B;     // 81920 B
    static int smem_set = 0;
    if (!smem_set) {
        cudaFuncSetAttribute(gemm_mma, cudaFuncAttributeMaxDynamicSharedMemorySize,
                             GEMM_SMEM);
        smem_set = 1;
    }

    int tb = 256;
    int n4 = M * 64, np4 = MP * 64;

    // ordered so gemm_mma is the 4th launch (ncu profile slot)
    prepA_k<<<(np4 + 255) / 256, 256>>>((const float4*)emb, n4, np4);   // 1
    prepW_k<<<512, 256>>>(Wl, Wr);                                      // 2
    zero_cnt_k<<<(M + tb - 1) / tb, tb>>>(M);                           // 3
    gemm_mma<<<dim3(4, T), 128, GEMM_SMEM>>>();                         // 4
    count_k<<<(E + tb - 1) / tb, tb>>>(ei, E);                          // 5
    int nb = (M + 1023) / 1024;
    scan1_k<<<nb, 1024>>>(M);                                           // 6
    scan2_k<<<1, 32>>>(nb);                                             // 7
    scan3_k<<<(M + tb - 1) / tb, tb>>>(M);                              // 8
    scatter_k<<<(E + tb - 1) / tb, tb>>>(ei, E);                        // 9
    agg_k<<<(M + 7) / 8, 256>>>(att, bias, out, M);                     // 10

    (void)n_in; (void)out_size;
}